// round 1
// baseline (speedup 1.0000x reference)
#include <cuda_runtime.h>

#define T 256
#define B 128
#define D 1024
#define K 21

__device__ float g_emissions[(size_t)T * B * K];
__device__ float g_loss_partial[B];

// ---------------------------------------------------------------------------
// Phase 1: emissions = features @ W + b
// 256 blocks x 96 threads; block tile = 128 rows x 21 cols; Dc=32 chunks.
// Thread tile: Rt=4 rows x Kt=7 cols (28 accumulators).
// ---------------------------------------------------------------------------
#define GROWS 128
#define DC 32

__global__ __launch_bounds__(96) void gemm_kernel(
    const float* __restrict__ A,      // [T*B, D]
    const float* __restrict__ W,      // [D, K]
    const float* __restrict__ bias)   // [K]
{
    __shared__ float a_sh[DC][GROWS + 1];   // +1 pad -> conflict-free staging
    __shared__ float w_sh[DC][K];

    const int tid = threadIdx.x;
    const int kg  = tid >> 5;    // 0..2  (k group of 7)
    const int rg  = tid & 31;    // 0..31 (row lane)
    const int row0 = blockIdx.x * GROWS;

    float acc[4][7];
#pragma unroll
    for (int r = 0; r < 4; r++)
#pragma unroll
        for (int k = 0; k < 7; k++) acc[r][k] = 0.0f;

    for (int dc = 0; dc < D; dc += DC) {
        // Stage A tile: 128 rows x 32 d, float4-coalesced.
        for (int i = tid; i < (GROWS * DC / 4); i += 96) {
            int r  = i >> 3;        // 0..127
            int dq = i & 7;         // 0..7 (quad of d)
            float4 v = *(const float4*)(A + (size_t)(row0 + r) * D + dc + dq * 4);
            a_sh[dq * 4 + 0][r] = v.x;
            a_sh[dq * 4 + 1][r] = v.y;
            a_sh[dq * 4 + 2][r] = v.z;
            a_sh[dq * 4 + 3][r] = v.w;
        }
        // Stage W chunk: 32 x 21.
        for (int j = tid; j < DC * K; j += 96) {
            int dd = j / K;
            int k  = j - dd * K;
            w_sh[dd][k] = W[(size_t)(dc + dd) * K + k];
        }
        __syncthreads();

#pragma unroll 4
        for (int dd = 0; dd < DC; dd++) {
            float a0 = a_sh[dd][rg];
            float a1 = a_sh[dd][rg + 32];
            float a2 = a_sh[dd][rg + 64];
            float a3 = a_sh[dd][rg + 96];
#pragma unroll
            for (int kk = 0; kk < 7; kk++) {
                float w = w_sh[dd][kg * 7 + kk];
                acc[0][kk] = fmaf(a0, w, acc[0][kk]);
                acc[1][kk] = fmaf(a1, w, acc[1][kk]);
                acc[2][kk] = fmaf(a2, w, acc[2][kk]);
                acc[3][kk] = fmaf(a3, w, acc[3][kk]);
            }
        }
        __syncthreads();
    }

#pragma unroll
    for (int rr = 0; rr < 4; rr++) {
        int row = row0 + rg + 32 * rr;
#pragma unroll
        for (int kk = 0; kk < 7; kk++) {
            int k = kg * 7 + kk;
            g_emissions[(size_t)row * K + k] = acc[rr][kk] + bias[k];
        }
    }
}

// ---------------------------------------------------------------------------
// Phase 2: Viterbi (warp 0) + forward logsumexp / NLL (warp 1).
// One block per batch (128 blocks x 64 threads).
// ---------------------------------------------------------------------------
__global__ __launch_bounds__(64) void scan_kernel(
    const int*   __restrict__ tags,    // [T, B]
    const float* __restrict__ start,   // [K]
    const float* __restrict__ endv,    // [K]
    const float* __restrict__ trans,   // [K, K]
    float* __restrict__ out)           // [T*B + 1]
{
    const int b    = blockIdx.x;
    const int warp = threadIdx.x >> 5;
    const int lane = threadIdx.x & 31;
    const bool act = (lane < K);
    const float NEG = -1e30f;

    __shared__ float sv[32];                 // viterbi score broadcast
    __shared__ float tf[32];                 // forward score broadcast
    __shared__ float se[32];                 // exp'd forward scores
    __shared__ unsigned char hist[(T - 1) * K];
    __shared__ unsigned char path[T];

    if (warp == 0) {
        // ------------------------- Viterbi -------------------------
        float tc[K];
#pragma unroll
        for (int i = 0; i < K; i++) tc[i] = act ? trans[i * K + lane] : 0.0f;

        float score = act ? (start[lane] + g_emissions[(size_t)b * K + lane]) : NEG;

        float emN = act ? g_emissions[(size_t)1 * B * K + (size_t)b * K + lane] : 0.0f;
        int   tgN = tags[1 * B + b];

        for (int t = 1; t < T; t++) {
            float em_t = emN;
            int   mk   = (tgN != 0);
            if (t + 1 < T) {
                emN = act ? g_emissions[(size_t)(t + 1) * B * K + (size_t)b * K + lane] : 0.0f;
                tgN = tags[(t + 1) * B + b];
            }
            sv[lane] = score;
            __syncwarp();

            // 3 parallel sub-chains, forward order => first-max kept (jnp.argmax)
            float m0 = NEG, m1 = NEG, m2 = NEG;
            int   i0 = 0,   i1 = 7,   i2 = 14;
#pragma unroll
            for (int i = 0; i < 7; i++)  { float c = sv[i] + tc[i];  if (c > m0) { m0 = c; i0 = i; } }
#pragma unroll
            for (int i = 7; i < 14; i++) { float c = sv[i] + tc[i];  if (c > m1) { m1 = c; i1 = i; } }
#pragma unroll
            for (int i = 14; i < 21; i++){ float c = sv[i] + tc[i];  if (c > m2) { m2 = c; i2 = i; } }
            float m = m0; int bi = i0;
            if (m1 > m) { m = m1; bi = i1; }
            if (m2 > m) { m = m2; bi = i2; }

            float nxt = m + em_t;
            int   ptr = mk ? bi : lane;
            if (act) hist[(t - 1) * K + lane] = (unsigned char)ptr;
            score = mk ? nxt : score;
            __syncwarp();
        }

        sv[lane] = act ? (score + endv[lane]) : NEG;
        __syncwarp();
        if (lane == 0) {
            float m = NEG; int bi = 0;
            for (int i = 0; i < K; i++) { float c = sv[i]; if (c > m) { m = c; bi = i; } }
            int cur = bi;
            path[T - 1] = (unsigned char)cur;
            for (int t = T - 2; t >= 0; t--) {
                cur = hist[t * K + cur];
                path[t] = (unsigned char)cur;
            }
        }
        __syncwarp();
        for (int t = lane; t < T; t += 32) {
            int mk = (tags[t * B + b] != 0);
            out[t * B + b] = mk ? (float)path[t] : 0.0f;
        }
    } else {
        // --------------------- Forward (lse) + NLL ---------------------
        float et[K];
#pragma unroll
        for (int i = 0; i < K; i++) et[i] = act ? __expf(trans[i * K + lane]) : 0.0f;

        float score = act ? (start[lane] + g_emissions[(size_t)b * K + lane]) : NEG;

        float emN = act ? g_emissions[(size_t)1 * B * K + (size_t)b * K + lane] : 0.0f;
        int   tgN = tags[1 * B + b];

        for (int t = 1; t < T; t++) {
            float em_t = emN;
            int   mk   = (tgN != 0);
            if (t + 1 < T) {
                emN = act ? g_emissions[(size_t)(t + 1) * B * K + (size_t)b * K + lane] : 0.0f;
                tgN = tags[(t + 1) * B + b];
            }
            tf[lane] = score;
            __syncwarp();

            float m0 = tf[0], m1 = tf[7], m2 = tf[14];
#pragma unroll
            for (int i = 1; i < 7; i++)   m0 = fmaxf(m0, tf[i]);
#pragma unroll
            for (int i = 8; i < 14; i++)  m1 = fmaxf(m1, tf[i]);
#pragma unroll
            for (int i = 15; i < 21; i++) m2 = fmaxf(m2, tf[i]);
            float m = fmaxf(m0, fmaxf(m1, m2));

            float e = __expf(score - m);   // lanes >= K: exp(-huge) = 0, harmless
            se[lane] = e;
            __syncwarp();

            float s0 = 0.f, s1 = 0.f, s2 = 0.f;
#pragma unroll
            for (int i = 0; i < 7; i++)   s0 = fmaf(se[i], et[i], s0);
#pragma unroll
            for (int i = 7; i < 14; i++)  s1 = fmaf(se[i], et[i], s1);
#pragma unroll
            for (int i = 14; i < 21; i++) s2 = fmaf(se[i], et[i], s2);
            float s = (s0 + s1) + s2;

            float nxt = m + __logf(s) + em_t;
            score = mk ? nxt : score;
            __syncwarp();
        }

        // denominator: lse(score + end)
        tf[lane] = act ? (score + endv[lane]) : NEG;
        __syncwarp();
        float m = tf[0];
        for (int i = 1; i < K; i++) m = fmaxf(m, tf[i]);
        float s = 0.0f;
        for (int i = 0; i < K; i++) s += __expf(tf[i] - m);
        float den = m + __logf(s);

        // numerator: gold path score (t-strided over lanes)
        float part = 0.0f;
        int   cnt  = 0;
        for (int t = lane; t < T; t += 32) {
            int tg = tags[t * B + b];
            if (tg != 0) {
                cnt++;
                if (t >= 1) {
                    int tp = tags[(t - 1) * B + b];
                    part += trans[tp * K + tg] +
                            g_emissions[(size_t)t * B * K + (size_t)b * K + tg];
                }
            }
        }
#pragma unroll
        for (int o = 16; o > 0; o >>= 1) {
            part += __shfl_down_sync(0xffffffffu, part, o);
            cnt  += __shfl_down_sync(0xffffffffu, cnt, o);
        }
        if (lane == 0) {
            int t0tag = tags[b];
            float num = start[t0tag] + g_emissions[(size_t)b * K + t0tag] + part;
            int seq_end = cnt - 1;
            int last = tags[seq_end * B + b];
            num += endv[last];
            g_loss_partial[b] = den - num;   // loss contribution = -(num - den)
        }
    }
}

// ---------------------------------------------------------------------------
// Phase 3: deterministic fixed-order tree reduction of per-batch losses.
// ---------------------------------------------------------------------------
__global__ __launch_bounds__(128) void loss_reduce(float* __restrict__ out)
{
    __shared__ float sh[B];
    int t = threadIdx.x;
    sh[t] = g_loss_partial[t];
    __syncthreads();
#pragma unroll
    for (int o = 64; o > 0; o >>= 1) {
        if (t < o) sh[t] += sh[t + o];
        __syncthreads();
    }
    if (t == 0) out[(size_t)T * B] = sh[0];
}

// ---------------------------------------------------------------------------
extern "C" void kernel_launch(void* const* d_in, const int* in_sizes, int n_in,
                              void* d_out, int out_size)
{
    const float* feat  = (const float*)d_in[0];   // lstm_features [T,B,D]
    const int*   tags  = (const int*)  d_in[1];   // tags [T,B]
    const float* W     = (const float*)d_in[2];   // [D,K]
    const float* bias  = (const float*)d_in[3];   // [K]
    const float* start = (const float*)d_in[4];   // [K]
    const float* endv  = (const float*)d_in[5];   // [K]
    const float* trans = (const float*)d_in[6];   // [K,K]
    float* out = (float*)d_out;                   // [T*B + 1] float32

    gemm_kernel<<<(T * B) / GROWS, 96>>>(feat, W, bias);
    scan_kernel<<<B, 64>>>(tags, start, endv, trans, out);
    loss_reduce<<<1, 128>>>(out);
}

// round 2
// speedup vs baseline: 1.3352x; 1.3352x over previous
#include <cuda_runtime.h>

#define T 256
#define B 128
#define D 1024
#define K 21

#define DSPLIT 4
#define DCHUNK (D / DSPLIT)      // 256
#define DC 32                    // d per stage
#define NSTAGE (DCHUNK / DC)     // 8
#define GROWS 128
#define GTHREADS 96
#define TBK (T * B * K)

typedef unsigned long long ull;

__device__ float g_part[DSPLIT * TBK];
__device__ float g_emissions[TBK];
__device__ float g_loss_partial[B];

__device__ __forceinline__ ull ffma2(ull a, ull b, ull c) {
    ull d;
    asm("fma.rn.f32x2 %0, %1, %2, %3;" : "=l"(d) : "l"(a), "l"(b), "l"(c));
    return d;
}
__device__ __forceinline__ ull pack2(float x, float y) {
    ull r;
    asm("mov.b64 %0, {%1, %2};" : "=l"(r) : "f"(x), "f"(y));
    return r;
}
__device__ __forceinline__ float2 unpack2(ull v) {
    float2 f;
    asm("mov.b64 {%0, %1}, %2;" : "=f"(f.x), "=f"(f.y) : "l"(v));
    return f;
}

// ---------------------------------------------------------------------------
// Phase 1: partial GEMM. Block = 128 rows x 21 k x 256 d-chunk.
// 96 threads: warp kg in {0,1,2} owns 7 k's; lane rg owns row pairs
// (rg, rg+64) and (rg+32, rg+96) packed as f32x2.
// ---------------------------------------------------------------------------
__global__ __launch_bounds__(GTHREADS) void gemm_kernel(
    const float* __restrict__ A,      // [T*B, D]
    const float* __restrict__ Wg)     // [D, K]
{
    __shared__ ull        a2u[DC][64];        // (row r | row r+64) packed, 16 KB
    __shared__ ulonglong2 w4u[K][DC / 2];     // ((w_d,w_d),(w_d1,w_d1)), 5.25 KB

    const int tid = threadIdx.x;
    const int kg  = tid >> 5;
    const int rg  = tid & 31;
    const int bid = blockIdx.x;
    const int rowblk = bid >> 2;
    const int split  = bid & 3;
    const int row0   = rowblk * GROWS;
    const int dbase  = split * DCHUNK;

    ull acc0[7], acc1[7];
#pragma unroll
    for (int k = 0; k < 7; k++) { acc0[k] = 0ull; acc1[k] = 0ull; }

    const float* Abase = A + (size_t)row0 * D + dbase;

    for (int s = 0; s < NSTAGE; s++) {
        const float* Ap = Abase + s * DC;
        // Stage A: 128 rows x 32 d, float4-coalesced reads.
        for (int i = tid; i < GROWS * DC / 4; i += GTHREADS) {
            int r  = i >> 3;
            int dq = i & 7;
            float4 v = *(const float4*)(Ap + (size_t)r * D + dq * 4);
            int half = r >> 6;
            int rl   = r & 63;
            ((float*)&a2u[dq * 4 + 0][rl])[half] = v.x;
            ((float*)&a2u[dq * 4 + 1][rl])[half] = v.y;
            ((float*)&a2u[dq * 4 + 2][rl])[half] = v.z;
            ((float*)&a2u[dq * 4 + 3][rl])[half] = v.w;
        }
        // Stage W: 32 d x 21 k, duplicated pairs for f32x2.
        int dc = dbase + s * DC;
        for (int j = tid; j < K * (DC / 2); j += GTHREADS) {
            int k   = j >> 4;
            int dd2 = j & 15;
            int d0  = dc + dd2 * 2;
            float w0 = Wg[(size_t)d0 * K + k];
            float w1 = Wg[(size_t)(d0 + 1) * K + k];
            w4u[k][dd2] = make_ulonglong2(pack2(w0, w0), pack2(w1, w1));
        }
        __syncthreads();

#pragma unroll
        for (int dd2 = 0; dd2 < DC / 2; dd2++) {
            ull a00 = a2u[2 * dd2][rg];
            ull a01 = a2u[2 * dd2][rg + 32];
            ull a10 = a2u[2 * dd2 + 1][rg];
            ull a11 = a2u[2 * dd2 + 1][rg + 32];
#pragma unroll
            for (int kk = 0; kk < 7; kk++) {
                ulonglong2 wv = w4u[kg * 7 + kk][dd2];
                acc0[kk] = ffma2(a00, wv.x, acc0[kk]);
                acc0[kk] = ffma2(a10, wv.y, acc0[kk]);
                acc1[kk] = ffma2(a01, wv.x, acc1[kk]);
                acc1[kk] = ffma2(a11, wv.y, acc1[kk]);
            }
        }
        __syncthreads();
    }

    float* P = g_part + (size_t)split * TBK;
#pragma unroll
    for (int kk = 0; kk < 7; kk++) {
        int k = kg * 7 + kk;
        float2 v0 = unpack2(acc0[kk]);
        float2 v1 = unpack2(acc1[kk]);
        P[(size_t)(row0 + rg) * K + k]      = v0.x;
        P[(size_t)(row0 + rg + 64) * K + k] = v0.y;
        P[(size_t)(row0 + rg + 32) * K + k] = v1.x;
        P[(size_t)(row0 + rg + 96) * K + k] = v1.y;
    }
}

// ---------------------------------------------------------------------------
// Phase 1b: reduce the 4 D-split partials + bias -> emissions (deterministic).
// ---------------------------------------------------------------------------
__global__ __launch_bounds__(256) void reduce_kernel(const float* __restrict__ bias)
{
    int i = blockIdx.x * 256 + threadIdx.x;
    if (i < TBK) {
        int k = i % K;
        float v = ((g_part[i] + g_part[i + TBK]) +
                   (g_part[i + 2 * TBK] + g_part[i + 3 * TBK])) + bias[k];
        g_emissions[i] = v;
    }
}

// ---------------------------------------------------------------------------
// Phase 2: Viterbi (warp 0) + normalized-weight forward / NLL (warp 1).
// One block per batch, shuffle-based broadcasts (no smem, no syncwarp in loop).
// ---------------------------------------------------------------------------
__global__ __launch_bounds__(64) void scan_kernel(
    const int*   __restrict__ tags,
    const float* __restrict__ start,
    const float* __restrict__ endv,
    const float* __restrict__ trans,
    float* __restrict__ out)
{
    const int b    = blockIdx.x;
    const int warp = threadIdx.x >> 5;
    const int lane = threadIdx.x & 31;
    const bool act = (lane < K);
    const float NEG = -1e30f;
    const unsigned FULL = 0xffffffffu;

    __shared__ unsigned char hist[(T - 1) * K];
    __shared__ unsigned char path[T];
    __shared__ float svf[32];

    if (warp == 0) {
        // ------------------------- Viterbi -------------------------
        float tc[K];
#pragma unroll
        for (int i = 0; i < K; i++) tc[i] = act ? trans[i * K + lane] : 0.0f;

        float score = act ? (start[lane] + g_emissions[(size_t)b * K + lane]) : NEG;

        float emN = act ? g_emissions[(size_t)B * K + (size_t)b * K + lane] : 0.0f;
        int   tgN = tags[B + b];

        for (int t = 1; t < T; t++) {
            float em_t = emN;
            int   mk   = (tgN != 0);
            if (t + 1 < T) {
                emN = act ? g_emissions[(size_t)(t + 1) * B * K + (size_t)b * K + lane] : 0.0f;
                tgN = tags[(t + 1) * B + b];
            }
            float s[K];
#pragma unroll
            for (int i = 0; i < K; i++) s[i] = __shfl_sync(FULL, score, i);

            float m0 = NEG, m1 = NEG, m2 = NEG;
            int   i0 = 0,   i1 = 7,   i2 = 14;
#pragma unroll
            for (int i = 0; i < 7; i++)   { float c = s[i] + tc[i];  if (c > m0) { m0 = c; i0 = i; } }
#pragma unroll
            for (int i = 7; i < 14; i++)  { float c = s[i] + tc[i];  if (c > m1) { m1 = c; i1 = i; } }
#pragma unroll
            for (int i = 14; i < 21; i++) { float c = s[i] + tc[i];  if (c > m2) { m2 = c; i2 = i; } }
            float m = m0; int bi = i0;
            if (m1 > m) { m = m1; bi = i1; }
            if (m2 > m) { m = m2; bi = i2; }

            int ptr = mk ? bi : lane;
            if (act) hist[(t - 1) * K + lane] = (unsigned char)ptr;
            score = mk ? (m + em_t) : score;
        }
        __syncwarp();

        svf[lane] = act ? (score + endv[lane]) : NEG;
        __syncwarp();
        if (lane == 0) {
            float m = NEG; int bi = 0;
            for (int i = 0; i < K; i++) { float c = svf[i]; if (c > m) { m = c; bi = i; } }
            int cur = bi;
            path[T - 1] = (unsigned char)cur;
            for (int t = T - 2; t >= 0; t--) {
                cur = hist[t * K + cur];
                path[t] = (unsigned char)cur;
            }
        }
        __syncwarp();
        for (int t = lane; t < T; t += 32) {
            int mk = (tags[t * B + b] != 0);
            out[t * B + b] = mk ? (float)path[t] : 0.0f;
        }
    } else {
        // --------- Forward in normalized-weight form + NLL ---------
        float et[K];
#pragma unroll
        for (int i = 0; i < K; i++) et[i] = act ? __expf(trans[i * K + lane]) : 0.0f;

        // t = 0: score0 = start + em0; normalize
        float em0 = act ? g_emissions[(size_t)b * K + lane] : NEG;
        float sc0 = act ? (start[lane] + em0) : NEG;
        float r0 = sc0;
#pragma unroll
        for (int o = 16; o > 0; o >>= 1) r0 = fmaxf(r0, __shfl_xor_sync(FULL, r0, o));
        float w = act ? __expf(sc0 - r0) : 0.0f;
        float C = r0;

        // prefetch t=1
        float emN = act ? g_emissions[(size_t)B * K + (size_t)b * K + lane] : NEG;
        int   tgN = tags[B + b];
        float rN = emN;
#pragma unroll
        for (int o = 16; o > 0; o >>= 1) rN = fmaxf(rN, __shfl_xor_sync(FULL, rN, o));
        float eemN = act ? __expf(emN - rN) : 0.0f;

        for (int t = 1; t < T; t++) {
            float eem = eemN;
            float r   = rN;
            int   mk  = (tgN != 0);
            if (t + 1 < T) {
                float em = act ? g_emissions[(size_t)(t + 1) * B * K + (size_t)b * K + lane] : NEG;
                tgN = tags[(t + 1) * B + b];
                float rr = em;
#pragma unroll
                for (int o = 16; o > 0; o >>= 1) rr = fmaxf(rr, __shfl_xor_sync(FULL, rr, o));
                rN   = rr;
                eemN = act ? __expf(em - rr) : 0.0f;
            }
            float wv[K];
#pragma unroll
            for (int i = 0; i < K; i++) wv[i] = __shfl_sync(FULL, w, i);

            float d0 = 0.f, d1 = 0.f, d2 = 0.f;
            float s0 = 0.f, s1 = 0.f, s2 = 0.f;
#pragma unroll
            for (int i = 0; i < 7; i++)   { d0 = fmaf(wv[i], et[i], d0); s0 += wv[i]; }
#pragma unroll
            for (int i = 7; i < 14; i++)  { d1 = fmaf(wv[i], et[i], d1); s1 += wv[i]; }
#pragma unroll
            for (int i = 14; i < 21; i++) { d2 = fmaf(wv[i], et[i], d2); s2 += wv[i]; }
            float d = (d0 + d1) + d2;
            float S = (s0 + s1) + s2;
            float rs;
            asm("rcp.approx.f32 %0, %1;" : "=f"(rs) : "f"(S));

            if (mk) {
                w = d * rs * eem;
                C += __logf(S) + r;
            }
        }

        // denominator
        float v = act ? (w * __expf(endv[lane])) : 0.0f;
#pragma unroll
        for (int o = 16; o > 0; o >>= 1) v += __shfl_xor_sync(FULL, v, o);
        float den = C + __logf(v);

        // numerator
        float part = 0.0f;
        int   cnt  = 0;
        for (int t = lane; t < T; t += 32) {
            int tg = tags[t * B + b];
            if (tg != 0) {
                cnt++;
                if (t >= 1) {
                    int tp = tags[(t - 1) * B + b];
                    part += trans[tp * K + tg] +
                            g_emissions[(size_t)t * B * K + (size_t)b * K + tg];
                }
            }
        }
#pragma unroll
        for (int o = 16; o > 0; o >>= 1) {
            part += __shfl_down_sync(FULL, part, o);
            cnt  += __shfl_down_sync(FULL, cnt, o);
        }
        if (lane == 0) {
            int t0tag = tags[b];
            float num = start[t0tag] + g_emissions[(size_t)b * K + t0tag] + part;
            int seq_end = cnt - 1;
            int last = tags[seq_end * B + b];
            num += endv[last];
            g_loss_partial[b] = den - num;
        }
    }
}

// ---------------------------------------------------------------------------
// Phase 3: deterministic loss tree reduction.
// ---------------------------------------------------------------------------
__global__ __launch_bounds__(128) void loss_reduce(float* __restrict__ out)
{
    __shared__ float sh[B];
    int t = threadIdx.x;
    sh[t] = g_loss_partial[t];
    __syncthreads();
#pragma unroll
    for (int o = 64; o > 0; o >>= 1) {
        if (t < o) sh[t] += sh[t + o];
        __syncthreads();
    }
    if (t == 0) out[(size_t)T * B] = sh[0];
}

// ---------------------------------------------------------------------------
extern "C" void kernel_launch(void* const* d_in, const int* in_sizes, int n_in,
                              void* d_out, int out_size)
{
    const float* feat  = (const float*)d_in[0];
    const int*   tags  = (const int*)  d_in[1];
    const float* W     = (const float*)d_in[2];
    const float* bias  = (const float*)d_in[3];
    const float* start = (const float*)d_in[4];
    const float* endv  = (const float*)d_in[5];
    const float* trans = (const float*)d_in[6];
    float* out = (float*)d_out;

    gemm_kernel<<<(T * B / GROWS) * DSPLIT, GTHREADS>>>(feat, W);
    reduce_kernel<<<(TBK + 255) / 256, 256>>>(bias);
    scan_kernel<<<B, 64>>>(tags, start, endv, trans, out);
    loss_reduce<<<1, 128>>>(out);
}